// round 13
// baseline (speedup 1.0000x reference)
#include <cuda_runtime.h>
#include <cuda_fp16.h>
#include <math.h>
#include <stdint.h>

#define WSZ 7
#define NTOK 49
#define CDIM 384
#define NHEAD 12
#define KDIM 32
#define BDIM 64
#define HDIM 28
#define LDIM 784
#define HIDD 1536
#define NWIN 1024
#define MROWS 50176
#define QKVO 1152

// ---------------- scratch ----------------
__device__ __half g_xn[(size_t)MROWS * CDIM];
__device__ __half g_qkv[(size_t)MROWS * QKVO];   // [win, head, tok, 96]
__device__ __half g_o[(size_t)MROWS * CDIM];     // attn out (window order)
__device__ float  g_x1[(size_t)MROWS * CDIM];    // after attn residual (B,L,C)
__device__ float  g_x2[(size_t)MROWS * CDIM];    // after conv+BN (B,L,C)
__device__ __half g_hmid[(size_t)MROWS * HIDD];  // MLP hidden
__device__ __half g_wh[442368 + 147456 + 589824 + 589824]; // half weights
__device__ float  g_biasp[NHEAD * 64 * 64];      // padded bias table

__device__ __forceinline__ int win_row_to_xl(int r) {
    int win = r / NTOK, n = r % NTOK;
    int b = win >> 4;
    int wh = (win >> 2) & 3, ww = win & 3;
    int ih = n / WSZ, iw = n % WSZ;
    int h = wh * WSZ + ih, w = ww * WSZ + iw;
    return b * LDIM + h * HDIM + w;
}

__device__ __forceinline__ uint32_t h2u(__half2 h) {
    union { __half2 h; uint32_t u; } cv;
    cv.h = h;
    return cv.u;
}
__device__ __forceinline__ uint32_t smem_u32(const void* p) {
    return (uint32_t)__cvta_generic_to_shared(p);
}

__device__ __forceinline__ void mma_f16(float c[4], uint32_t a0, uint32_t a1,
                                        uint32_t a2, uint32_t a3,
                                        uint32_t b0, uint32_t b1) {
    asm volatile(
        "mma.sync.aligned.m16n8k16.row.col.f32.f16.f16.f32 "
        "{%0,%1,%2,%3}, {%4,%5,%6,%7}, {%8,%9}, {%0,%1,%2,%3};"
        : "+f"(c[0]), "+f"(c[1]), "+f"(c[2]), "+f"(c[3])
        : "r"(a0), "r"(a1), "r"(a2), "r"(a3), "r"(b0), "r"(b1));
}

__device__ __forceinline__ void cp16(void* dst, const void* src) {
    uint32_t d = smem_u32(dst);
    asm volatile("cp.async.cg.shared.global [%0], [%1], 16;" :: "r"(d), "l"(src));
}
__device__ __forceinline__ void cp_commit() { asm volatile("cp.async.commit_group;"); }
template<int N> __device__ __forceinline__ void cp_wait() {
    asm volatile("cp.async.wait_group %0;" :: "n"(N));
}
__device__ __forceinline__ void ldsm4(uint32_t& r0, uint32_t& r1, uint32_t& r2,
                                      uint32_t& r3, const void* p) {
    uint32_t a = smem_u32(p);
    asm volatile("ldmatrix.sync.aligned.m8n8.x4.shared.b16 {%0,%1,%2,%3}, [%4];"
                 : "=r"(r0), "=r"(r1), "=r"(r2), "=r"(r3) : "r"(a));
}
__device__ __forceinline__ void ldsm2(uint32_t& r0, uint32_t& r1, const void* p) {
    uint32_t a = smem_u32(p);
    asm volatile("ldmatrix.sync.aligned.m8n8.x2.shared.b16 {%0,%1}, [%2];"
                 : "=r"(r0), "=r"(r1) : "r"(a));
}

// ---------------- all weights fp32 -> fp16 (one launch, float4 vectorized) ----------------
#define WN0 442368
#define WN1 (WN0 + 147456)
#define WN2 (WN1 + 589824)
#define WN3 (WN2 + 589824)
__global__ void __launch_bounds__(256)
w2h_all(const float* __restrict__ a, const float* __restrict__ b,
        const float* __restrict__ c, const float* __restrict__ d,
        __half* __restrict__ out) {
    int idx = (blockIdx.x * 256 + threadIdx.x) * 4;
    if (idx >= WN3) return;
    const float* src;
    int off;
    if (idx < WN0)      { src = a; off = idx; }
    else if (idx < WN1) { src = b; off = idx - WN0; }
    else if (idx < WN2) { src = c; off = idx - WN1; }
    else                { src = d; off = idx - WN2; }
    float4 v = *(const float4*)(src + off);
    __half2 h0 = __floats2half2_rn(v.x, v.y);
    __half2 h1 = __floats2half2_rn(v.z, v.w);
    uint2 pk = make_uint2(h2u(h0), h2u(h1));
    *(uint2*)(out + idx) = pk;
}

// ---------------- bias table expand ----------------
__global__ void __launch_bounds__(256)
bias_prep(const float* __restrict__ attn_bias, const int* __restrict__ bias_idxs,
          float* __restrict__ biasp) {
    int h = blockIdx.x;
    for (int e = threadIdx.x; e < 4096; e += 256) {
        int i = e >> 6, j = e & 63;
        float v;
        if (j >= NTOK) v = -1e30f;
        else if (i >= NTOK) v = 0.f;
        else v = attn_bias[h * NTOK + bias_idxs[i * NTOK + j]];
        biasp[h * 4096 + e] = v;
    }
}

// ---------------- windowed LayerNorm (half output) ----------------
__global__ void __launch_bounds__(256)
ln_kernel(const float* __restrict__ x, const float* __restrict__ g,
          const float* __restrict__ bvec, __half* __restrict__ out)
{
    int r = blockIdx.x * 8 + (threadIdx.x >> 5);
    int lane = threadIdx.x & 31;
    if (r >= MROWS) return;
    const float* src = x + (size_t)win_row_to_xl(r) * CDIM;
    float vals[12];
    float s = 0.f, s2 = 0.f;
#pragma unroll
    for (int i = 0; i < 12; i++) {
        float v = src[lane + 32 * i];
        vals[i] = v;
        s += v;
        s2 = fmaf(v, v, s2);
    }
#pragma unroll
    for (int o = 16; o; o >>= 1) {
        s  += __shfl_xor_sync(0xffffffffu, s,  o);
        s2 += __shfl_xor_sync(0xffffffffu, s2, o);
    }
    float mean = s * (1.f / CDIM);
    float var  = s2 * (1.f / CDIM) - mean * mean;
    float inv  = rsqrtf(var + 1e-5f);
    __half* dst = out + (size_t)r * CDIM;
#pragma unroll
    for (int i = 0; i < 12; i++) {
        int c = lane + 32 * i;
        dst[c] = __float2half_rn((vals[i] - mean) * inv * g[c] + bvec[c]);
    }
}

// ------- fp16 GEMM: CTA 128x128x64, 3-stage cp.async ring, ONE sync/iter, 2 CTAs/SM -------
// 8 warps (4m x 2n), warp tile 32x64 = 2x8 m16n8k16 tiles, BK=64 (4 ksteps).
// B fragments loaded pairwise via ldsm4 (2 n-tiles per instruction).
// MODE 0: QKV scatter(half)  MODE 1: proj+res->f32  MODE 2: FC1+GELU(half)  MODE 3: FC2+res->f32
#define HP 72
#define STGH (256 * HP)                      // halves per stage (128 A rows + 128 B rows)
#define GEMM_SMEM (3 * STGH * 2)             // 108 KB
template<int MODE>
__global__ void __launch_bounds__(256, 2)
gemm_h(const __half* __restrict__ A, const __half* __restrict__ W,
       const float* __restrict__ bias, void* __restrict__ outv,
       int K, int Ncols, const float* __restrict__ res)
{
    extern __shared__ __half sm[];
    const int tid  = threadIdx.x;
    const int warp = tid >> 5, lane = tid & 31;
    const int wm = warp & 3, wn = warp >> 2;
    const int qr = lane >> 2, qc = lane & 3;
    const int m0 = blockIdx.y * 128, n0 = blockIdx.x * 128;

    const int rowb = tid >> 3;             // 0..31
    const int cseg = (tid & 7) * 8;        // halves: 0..56
    const __half* Ag = A + (size_t)(m0 + rowb) * K + cseg;
    const __half* Wg = W + (size_t)(n0 + rowb) * K + cseg;

    float acc[2][8][4] = {};
    const int niter = K >> 6;

    // prologue: stages 0 and 1, one commit group each
#pragma unroll
    for (int st = 0; st < 2; st++) {
        __half* Ad = sm + st * STGH + rowb * HP + cseg;
        __half* Bd = sm + st * STGH + 128 * HP + rowb * HP + cseg;
        int k0 = st << 6;
#pragma unroll
        for (int i = 0; i < 4; i++) cp16(Ad + i * 32 * HP, Ag + k0 + (size_t)i * 32 * K);
#pragma unroll
        for (int i = 0; i < 4; i++) cp16(Bd + i * 32 * HP, Wg + k0 + (size_t)i * 32 * K);
        cp_commit();
    }

    for (int it = 0; it < niter; it++) {
        cp_wait<1>();                 // group `it` complete; `it+1` may be in flight
        __syncthreads();              // all warps done reading stage (it-1)%3 -> safe to write (it+2)%3
        int cur = it % 3;
        const __half* Ab = sm + cur * STGH + wm * 32 * HP;
        const __half* Bb = sm + cur * STGH + 128 * HP + wn * 64 * HP;
#pragma unroll
        for (int ks = 0; ks < 4; ks++) {
            int kb = ks * 16;
            uint32_t af[2][4], bf[8][2];
#pragma unroll
            for (int mt = 0; mt < 2; mt++)
                ldsm4(af[mt][0], af[mt][1], af[mt][2], af[mt][3],
                      Ab + (mt * 16 + (lane & 15)) * HP + kb + (lane >> 4) * 8);
#pragma unroll
            for (int np = 0; np < 4; np++)
                ldsm4(bf[2 * np][0], bf[2 * np + 1][0], bf[2 * np][1], bf[2 * np + 1][1],
                      Bb + (np * 16 + (lane & 15)) * HP + kb + (lane >> 4) * 8);
#pragma unroll
            for (int mt = 0; mt < 2; mt++)
#pragma unroll
                for (int nt = 0; nt < 8; nt++)
                    mma_f16(acc[mt][nt], af[mt][0], af[mt][1], af[mt][2], af[mt][3],
                            bf[nt][0], bf[nt][1]);
        }
        if (it + 2 < niter) {
            int st = (it + 2) % 3;
            int k0 = (it + 2) << 6;
            __half* Ad = sm + st * STGH + rowb * HP + cseg;
            __half* Bd = sm + st * STGH + 128 * HP + rowb * HP + cseg;
#pragma unroll
            for (int i = 0; i < 4; i++) cp16(Ad + i * 32 * HP, Ag + k0 + (size_t)i * 32 * K);
#pragma unroll
            for (int i = 0; i < 4; i++) cp16(Bd + i * 32 * HP, Wg + k0 + (size_t)i * 32 * K);
        }
        cp_commit();                  // commit (possibly empty) -> keeps group count aligned
    }

    // epilogue: paired (half2/float2) stores
#pragma unroll
    for (int mt = 0; mt < 2; mt++) {
        int mA = m0 + wm * 32 + mt * 16 + qr;
        int mB = mA + 8;
#pragma unroll
        for (int nt = 0; nt < 8; nt++) {
            int n = n0 + wn * 64 + nt * 8 + qc * 2;
            float b0 = bias[n], b1 = bias[n + 1];
            float v0 = acc[mt][nt][0] + b0, v1 = acc[mt][nt][1] + b1;
            float v2 = acc[mt][nt][2] + b0, v3 = acc[mt][nt][3] + b1;
            if (MODE == 0) {
                int head = n / 96, t = n % 96;
                {
                    int win = mA / NTOK, tok = mA % NTOK;
                    *(__half2*)&((__half*)outv)[((size_t)(win * NHEAD + head) * NTOK + tok) * 96 + t]
                        = __floats2half2_rn(v0, v1);
                }
                {
                    int win = mB / NTOK, tok = mB % NTOK;
                    *(__half2*)&((__half*)outv)[((size_t)(win * NHEAD + head) * NTOK + tok) * 96 + t]
                        = __floats2half2_rn(v2, v3);
                }
            } else if (MODE == 1) {
                {
                    int xl = win_row_to_xl(mA);
                    float2 r = *(const float2*)&res[(size_t)xl * CDIM + n];
                    *(float2*)&((float*)outv)[(size_t)xl * CDIM + n] =
                        make_float2(r.x + v0, r.y + v1);
                }
                {
                    int xl = win_row_to_xl(mB);
                    float2 r = *(const float2*)&res[(size_t)xl * CDIM + n];
                    *(float2*)&((float*)outv)[(size_t)xl * CDIM + n] =
                        make_float2(r.x + v2, r.y + v3);
                }
            } else if (MODE == 2) {
                float g0 = 0.5f * v0 * (1.f + erff(v0 * 0.70710678118654752f));
                float g1 = 0.5f * v1 * (1.f + erff(v1 * 0.70710678118654752f));
                float g2 = 0.5f * v2 * (1.f + erff(v2 * 0.70710678118654752f));
                float g3 = 0.5f * v3 * (1.f + erff(v3 * 0.70710678118654752f));
                *(__half2*)&((__half*)outv)[(size_t)mA * Ncols + n] = __floats2half2_rn(g0, g1);
                *(__half2*)&((__half*)outv)[(size_t)mB * Ncols + n] = __floats2half2_rn(g2, g3);
            } else {
                float2 rA = *(const float2*)&res[(size_t)mA * Ncols + n];
                float2 rB = *(const float2*)&res[(size_t)mB * Ncols + n];
                *(float2*)&((float*)outv)[(size_t)mA * Ncols + n] =
                    make_float2(rA.x + v0, rA.y + v1);
                *(float2*)&((float*)outv)[(size_t)mB * Ncols + n] =
                    make_float2(rB.x + v2, rB.y + v3);
            }
        }
    }
}

// ---------------- tensor-core attention: one block per (win, head) ----------------
#define QP 40
#define VP 72
__global__ void __launch_bounds__(128)
attn_tc(const __half* __restrict__ qkv, const float* __restrict__ biasp,
        __half* __restrict__ o)
{
    int wh = blockIdx.x;
    int win = wh / NHEAD, head = wh % NHEAD;
    __shared__ __half Qs[64 * QP];
    __shared__ __half Ks[64 * QP];
    __shared__ __half Vt[32 * VP];
    int tid = threadIdx.x;

    for (int i = tid; i < 64 * QP / 2; i += 128) {
        ((uint32_t*)Qs)[i] = 0;
        ((uint32_t*)Ks)[i] = 0;
    }
    for (int i = tid; i < 32 * VP / 2; i += 128) ((uint32_t*)Vt)[i] = 0;
    __syncthreads();

    const uint4* src = (const uint4*)(qkv + (size_t)wh * NTOK * 96);
    for (int idx = tid; idx < 588; idx += 128) {
        uint4 v = src[idx];
        int row = idx / 12, seg = idx % 12;
        if (seg < 4)      *(uint4*)(Qs + row * QP + seg * 8) = v;
        else if (seg < 8) *(uint4*)(Ks + row * QP + (seg - 4) * 8) = v;
        else {
            int d0 = (seg - 8) * 8;
            __half h[8];
            *(uint4*)h = v;
#pragma unroll
            for (int t = 0; t < 8; t++) Vt[(d0 + t) * VP + row] = h[t];
        }
    }
    __syncthreads();

    int warp = tid >> 5, lane = tid & 31;
    int qr = lane >> 2, qc = lane & 3;

    float sc[8][4] = {};
#pragma unroll
    for (int ks = 0; ks < 2; ks++) {
        int kb = ks * 16;
        uint32_t a0, a1, a2, a3;
        ldsm4(a0, a1, a2, a3, Qs + (warp * 16 + (lane & 15)) * QP + kb + (lane >> 4) * 8);
#pragma unroll
        for (int nt = 0; nt < 8; nt++) {
            uint32_t b0, b1;
            ldsm2(b0, b1, Ks + (nt * 8 + (lane & 7)) * QP + kb + ((lane >> 3) & 1) * 8);
            mma_f16(sc[nt], a0, a1, a2, a3, b0, b1);
        }
    }

    const float scale = 0.1767766952966369f;
    const float* bp = biasp + (head * 64 + warp * 16) * 64;
    float m0 = -1e30f, m1 = -1e30f;
#pragma unroll
    for (int nt = 0; nt < 8; nt++) {
        int col = nt * 8 + qc * 2;
        sc[nt][0] = fmaf(sc[nt][0], scale, bp[qr * 64 + col]);
        sc[nt][1] = fmaf(sc[nt][1], scale, bp[qr * 64 + col + 1]);
        sc[nt][2] = fmaf(sc[nt][2], scale, bp[(qr + 8) * 64 + col]);
        sc[nt][3] = fmaf(sc[nt][3], scale, bp[(qr + 8) * 64 + col + 1]);
        m0 = fmaxf(m0, fmaxf(sc[nt][0], sc[nt][1]));
        m1 = fmaxf(m1, fmaxf(sc[nt][2], sc[nt][3]));
    }
#pragma unroll
    for (int off = 1; off < 4; off <<= 1) {
        m0 = fmaxf(m0, __shfl_xor_sync(0xffffffffu, m0, off));
        m1 = fmaxf(m1, __shfl_xor_sync(0xffffffffu, m1, off));
    }
    float s0 = 0.f, s1 = 0.f;
#pragma unroll
    for (int nt = 0; nt < 8; nt++) {
        sc[nt][0] = __expf(sc[nt][0] - m0);
        sc[nt][1] = __expf(sc[nt][1] - m0);
        sc[nt][2] = __expf(sc[nt][2] - m1);
        sc[nt][3] = __expf(sc[nt][3] - m1);
        s0 += sc[nt][0] + sc[nt][1];
        s1 += sc[nt][2] + sc[nt][3];
    }
#pragma unroll
    for (int off = 1; off < 4; off <<= 1) {
        s0 += __shfl_xor_sync(0xffffffffu, s0, off);
        s1 += __shfl_xor_sync(0xffffffffu, s1, off);
    }
    float i0 = 1.f / s0, i1 = 1.f / s1;
    uint32_t p01[8], p23[8];
#pragma unroll
    for (int nt = 0; nt < 8; nt++) {
        p01[nt] = h2u(__floats2half2_rn(sc[nt][0] * i0, sc[nt][1] * i0));
        p23[nt] = h2u(__floats2half2_rn(sc[nt][2] * i1, sc[nt][3] * i1));
    }

    float oc[4][4] = {};
#pragma unroll
    for (int ks = 0; ks < 4; ks++) {
        uint32_t a0 = p01[2 * ks], a1 = p23[2 * ks];
        uint32_t a2 = p01[2 * ks + 1], a3 = p23[2 * ks + 1];
#pragma unroll
        for (int nt = 0; nt < 4; nt++) {
            uint32_t b0, b1;
            ldsm2(b0, b1, Vt + (nt * 8 + (lane & 7)) * VP + ks * 16 + ((lane >> 3) & 1) * 8);
            mma_f16(oc[nt], a0, a1, a2, a3, b0, b1);
        }
    }

    int r0 = warp * 16 + qr, r1 = r0 + 8;
#pragma unroll
    for (int nt = 0; nt < 4; nt++) {
        int col = head * KDIM + nt * 8 + qc * 2;
        if (r0 < NTOK)
            *(__half2*)&o[((size_t)(win * NTOK + r0)) * CDIM + col] =
                __floats2half2_rn(oc[nt][0], oc[nt][1]);
        if (r1 < NTOK)
            *(__half2*)&o[((size_t)(win * NTOK + r1)) * CDIM + col] =
                __floats2half2_rn(oc[nt][2], oc[nt][3]);
    }
}

// ---------------- depthwise conv + BN + LN (fused) ----------------
__global__ void __launch_bounds__(128)
conv_bn_ln(const float* __restrict__ x1, const float* __restrict__ cw,
           const float* __restrict__ bng, const float* __restrict__ bnb,
           const float* __restrict__ bnm, const float* __restrict__ bnv,
           const float* __restrict__ lng, const float* __restrict__ lnb,
           float* __restrict__ x2, __half* __restrict__ xn)
{
    int bl = blockIdx.x;
    int b = bl / LDIM, l = bl % LDIM;
    int h = l / HDIM, w = l % HDIM;
    float vals[3];
    float s = 0.f, s2 = 0.f;
#pragma unroll
    for (int q = 0; q < 3; q++) {
        int c = threadIdx.x + q * 128;
        float acc = 0.f;
#pragma unroll
        for (int dh = -1; dh <= 1; dh++) {
            int hh = h + dh;
            if (hh < 0 || hh >= HDIM) continue;
#pragma unroll
            for (int dw = -1; dw <= 1; dw++) {
                int ww = w + dw;
                if (ww < 0 || ww >= HDIM) continue;
                acc = fmaf(x1[((size_t)b * LDIM + hh * HDIM + ww) * CDIM + c],
                           cw[c * 9 + (dh + 1) * 3 + (dw + 1)], acc);
            }
        }
        float inv = rsqrtf(bnv[c] + 1e-5f);
        float v = (acc - bnm[c]) * bng[c] * inv + bnb[c];
        vals[q] = v;
        x2[(size_t)bl * CDIM + c] = v;
        s += v;
        s2 = fmaf(v, v, s2);
    }
    __shared__ float reds[4], reds2[4];
    int lane = threadIdx.x & 31, warp = threadIdx.x >> 5;
#pragma unroll
    for (int o = 16; o; o >>= 1) {
        s  += __shfl_xor_sync(0xffffffffu, s,  o);
        s2 += __shfl_xor_sync(0xffffffffu, s2, o);
    }
    if (lane == 0) { reds[warp] = s; reds2[warp] = s2; }
    __syncthreads();
    s  = reds[0] + reds[1] + reds[2] + reds[3];
    s2 = reds2[0] + reds2[1] + reds2[2] + reds2[3];
    float mean = s * (1.f / CDIM);
    float var  = s2 * (1.f / CDIM) - mean * mean;
    float inv  = rsqrtf(var + 1e-5f);
#pragma unroll
    for (int q = 0; q < 3; q++) {
        int c = threadIdx.x + q * 128;
        xn[(size_t)bl * CDIM + c] =
            __float2half_rn((vals[q] - mean) * inv * lng[c] + lnb[c]);
    }
}

// ---------------- launch ----------------
static void* symptr(const void* s) {
    void* p = nullptr;
    cudaGetSymbolAddress(&p, s);
    return p;
}

extern "C" void kernel_launch(void* const* d_in, const int* in_sizes, int n_in,
                              void* d_out, int out_size)
{
    const float* x        = (const float*)d_in[0];
    const float* ln_a_g   = (const float*)d_in[1];
    const float* ln_a_b   = (const float*)d_in[2];
    const float* qkv_w    = (const float*)d_in[3];
    const float* qkv_b    = (const float*)d_in[4];
    const float* attn_bias= (const float*)d_in[5];
    const float* proj_w   = (const float*)d_in[6];
    const float* proj_b   = (const float*)d_in[7];
    const float* conv_w   = (const float*)d_in[8];
    const float* bn_g     = (const float*)d_in[9];
    const float* bn_b     = (const float*)d_in[10];
    const float* bn_m     = (const float*)d_in[11];
    const float* bn_v     = (const float*)d_in[12];
    const float* ln_m_g   = (const float*)d_in[13];
    const float* ln_m_b   = (const float*)d_in[14];
    const float* fc1_w    = (const float*)d_in[15];
    const float* fc1_b    = (const float*)d_in[16];
    const float* fc2_w    = (const float*)d_in[17];
    const float* fc2_b    = (const float*)d_in[18];
    const int*   bias_idxs= (const int*)d_in[19];
    float* out = (float*)d_out;

    __half* xn    = (__half*)symptr(g_xn);
    __half* qkv   = (__half*)symptr(g_qkv);
    __half* ob    = (__half*)symptr(g_o);
    float*  x1    = (float*)symptr(g_x1);
    float*  x2    = (float*)symptr(g_x2);
    __half* hmid  = (__half*)symptr(g_hmid);
    __half* wbuf  = (__half*)symptr(g_wh);
    float*  biasp = (float*)symptr(g_biasp);

    __half* wq = wbuf;
    __half* wp = wbuf + WN0;
    __half* w1 = wbuf + WN1;
    __half* w2 = wbuf + WN2;

    cudaFuncSetAttribute(gemm_h<0>, cudaFuncAttributeMaxDynamicSharedMemorySize, GEMM_SMEM);
    cudaFuncSetAttribute(gemm_h<1>, cudaFuncAttributeMaxDynamicSharedMemorySize, GEMM_SMEM);
    cudaFuncSetAttribute(gemm_h<2>, cudaFuncAttributeMaxDynamicSharedMemorySize, GEMM_SMEM);
    cudaFuncSetAttribute(gemm_h<3>, cudaFuncAttributeMaxDynamicSharedMemorySize, GEMM_SMEM);

    w2h_all<<<WN3 / 1024, 256>>>(qkv_w, proj_w, fc1_w, fc2_w, wbuf);
    bias_prep<<<NHEAD, 256>>>(attn_bias, bias_idxs, biasp);

    ln_kernel<<<MROWS / 8, 256>>>(x, ln_a_g, ln_a_b, xn);
    gemm_h<0><<<dim3(QKVO / 128, MROWS / 128), 256, GEMM_SMEM>>>(xn, wq, qkv_b, qkv, CDIM, QKVO, nullptr);
    attn_tc<<<NWIN * NHEAD, 128>>>(qkv, biasp, ob);
    gemm_h<1><<<dim3(CDIM / 128, MROWS / 128), 256, GEMM_SMEM>>>(ob, wp, proj_b, x1, CDIM, CDIM, x);
    conv_bn_ln<<<BDIM * LDIM, 128>>>(x1, conv_w, bn_g, bn_b, bn_m, bn_v,
                                     ln_m_g, ln_m_b, x2, xn);
    gemm_h<2><<<dim3(HIDD / 128, MROWS / 128), 256, GEMM_SMEM>>>(xn, w1, fc1_b, hmid, CDIM, HIDD, nullptr);
    gemm_h<3><<<dim3(CDIM / 128, MROWS / 128), 256, GEMM_SMEM>>>(hmid, w2, fc2_b, out, HIDD, CDIM, x2);
}

// round 14
// speedup vs baseline: 1.0966x; 1.0966x over previous
#include <cuda_runtime.h>
#include <cuda_fp16.h>
#include <math.h>
#include <stdint.h>

#define WSZ 7
#define NTOK 49
#define CDIM 384
#define NHEAD 12
#define KDIM 32
#define BDIM 64
#define HDIM 28
#define LDIM 784
#define HIDD 1536
#define NWIN 1024
#define MROWS 50176
#define QKVO 1152

// ---------------- scratch ----------------
__device__ __half g_xn[(size_t)MROWS * CDIM];
__device__ __half g_qkv[(size_t)MROWS * QKVO];   // [win, head, tok, 96]
__device__ __half g_o[(size_t)MROWS * CDIM];     // attn out (window order)
__device__ float  g_x1[(size_t)MROWS * CDIM];    // after attn residual (B,L,C)
__device__ float  g_x2[(size_t)MROWS * CDIM];    // after conv+BN (B,L,C)
__device__ __half g_hmid[(size_t)MROWS * HIDD];  // MLP hidden
__device__ __half g_wh[442368 + 147456 + 589824 + 589824]; // half weights
__device__ float  g_biasp[NHEAD * 64 * 64];      // padded bias table

__device__ __forceinline__ int win_row_to_xl(int r) {
    int win = r / NTOK, n = r % NTOK;
    int b = win >> 4;
    int wh = (win >> 2) & 3, ww = win & 3;
    int ih = n / WSZ, iw = n % WSZ;
    int h = wh * WSZ + ih, w = ww * WSZ + iw;
    return b * LDIM + h * HDIM + w;
}

__device__ __forceinline__ uint32_t h2u(__half2 h) {
    union { __half2 h; uint32_t u; } cv;
    cv.h = h;
    return cv.u;
}
__device__ __forceinline__ uint32_t smem_u32(const void* p) {
    return (uint32_t)__cvta_generic_to_shared(p);
}

__device__ __forceinline__ void mma_f16(float c[4], uint32_t a0, uint32_t a1,
                                        uint32_t a2, uint32_t a3,
                                        uint32_t b0, uint32_t b1) {
    asm volatile(
        "mma.sync.aligned.m16n8k16.row.col.f32.f16.f16.f32 "
        "{%0,%1,%2,%3}, {%4,%5,%6,%7}, {%8,%9}, {%0,%1,%2,%3};"
        : "+f"(c[0]), "+f"(c[1]), "+f"(c[2]), "+f"(c[3])
        : "r"(a0), "r"(a1), "r"(a2), "r"(a3), "r"(b0), "r"(b1));
}

__device__ __forceinline__ void cp16(void* dst, const void* src) {
    uint32_t d = smem_u32(dst);
    asm volatile("cp.async.cg.shared.global [%0], [%1], 16;" :: "r"(d), "l"(src));
}
__device__ __forceinline__ void cp_commit() { asm volatile("cp.async.commit_group;"); }
template<int N> __device__ __forceinline__ void cp_wait() {
    asm volatile("cp.async.wait_group %0;" :: "n"(N));
}
__device__ __forceinline__ void ldsm4(uint32_t& r0, uint32_t& r1, uint32_t& r2,
                                      uint32_t& r3, const void* p) {
    uint32_t a = smem_u32(p);
    asm volatile("ldmatrix.sync.aligned.m8n8.x4.shared.b16 {%0,%1,%2,%3}, [%4];"
                 : "=r"(r0), "=r"(r1), "=r"(r2), "=r"(r3) : "r"(a));
}
__device__ __forceinline__ void ldsm2(uint32_t& r0, uint32_t& r1, const void* p) {
    uint32_t a = smem_u32(p);
    asm volatile("ldmatrix.sync.aligned.m8n8.x2.shared.b16 {%0,%1}, [%2];"
                 : "=r"(r0), "=r"(r1) : "r"(a));
}

// ---------------- all weights fp32 -> fp16 (one launch, float4 vectorized) ----------------
#define WN0 442368
#define WN1 (WN0 + 147456)
#define WN2 (WN1 + 589824)
#define WN3 (WN2 + 589824)
__global__ void __launch_bounds__(256)
w2h_all(const float* __restrict__ a, const float* __restrict__ b,
        const float* __restrict__ c, const float* __restrict__ d,
        __half* __restrict__ out) {
    int idx = (blockIdx.x * 256 + threadIdx.x) * 4;
    if (idx >= WN3) return;
    const float* src;
    int off;
    if (idx < WN0)      { src = a; off = idx; }
    else if (idx < WN1) { src = b; off = idx - WN0; }
    else if (idx < WN2) { src = c; off = idx - WN1; }
    else                { src = d; off = idx - WN2; }
    float4 v = *(const float4*)(src + off);
    __half2 h0 = __floats2half2_rn(v.x, v.y);
    __half2 h1 = __floats2half2_rn(v.z, v.w);
    uint2 pk = make_uint2(h2u(h0), h2u(h1));
    *(uint2*)(out + idx) = pk;
}

// ---------------- bias table expand ----------------
__global__ void __launch_bounds__(256)
bias_prep(const float* __restrict__ attn_bias, const int* __restrict__ bias_idxs,
          float* __restrict__ biasp) {
    int h = blockIdx.x;
    for (int e = threadIdx.x; e < 4096; e += 256) {
        int i = e >> 6, j = e & 63;
        float v;
        if (j >= NTOK) v = -1e30f;
        else if (i >= NTOK) v = 0.f;
        else v = attn_bias[h * NTOK + bias_idxs[i * NTOK + j]];
        biasp[h * 4096 + e] = v;
    }
}

// ---------------- windowed LayerNorm (half output) ----------------
__global__ void __launch_bounds__(256)
ln_kernel(const float* __restrict__ x, const float* __restrict__ g,
          const float* __restrict__ bvec, __half* __restrict__ out)
{
    int r = blockIdx.x * 8 + (threadIdx.x >> 5);
    int lane = threadIdx.x & 31;
    if (r >= MROWS) return;
    const float* src = x + (size_t)win_row_to_xl(r) * CDIM;
    float vals[12];
    float s = 0.f, s2 = 0.f;
#pragma unroll
    for (int i = 0; i < 12; i++) {
        float v = src[lane + 32 * i];
        vals[i] = v;
        s += v;
        s2 = fmaf(v, v, s2);
    }
#pragma unroll
    for (int o = 16; o; o >>= 1) {
        s  += __shfl_xor_sync(0xffffffffu, s,  o);
        s2 += __shfl_xor_sync(0xffffffffu, s2, o);
    }
    float mean = s * (1.f / CDIM);
    float var  = s2 * (1.f / CDIM) - mean * mean;
    float inv  = rsqrtf(var + 1e-5f);
    __half* dst = out + (size_t)r * CDIM;
#pragma unroll
    for (int i = 0; i < 12; i++) {
        int c = lane + 32 * i;
        dst[c] = __float2half_rn((vals[i] - mean) * inv * g[c] + bvec[c]);
    }
}

// ------- fp16 GEMM (R12): CTA 128x128x64, 3-stage cp.async ring, ONE sync/iter, 2 CTAs/SM -------
// 8 warps (4m x 2n), warp tile 32x64 = 2x8 m16n8k16 tiles, BK=64 (4 ksteps).
// MODE 0: QKV scatter(half)  MODE 1: proj+res->f32  MODE 2: FC1+GELU(half)  MODE 3: FC2+res->f32
#define HP 72
#define STGH (256 * HP)
#define GEMM_SMEM (3 * STGH * 2)
template<int MODE>
__global__ void __launch_bounds__(256, 2)
gemm_h(const __half* __restrict__ A, const __half* __restrict__ W,
       const float* __restrict__ bias, void* __restrict__ outv,
       int K, int Ncols, const float* __restrict__ res)
{
    extern __shared__ __half sm[];
    const int tid  = threadIdx.x;
    const int warp = tid >> 5, lane = tid & 31;
    const int wm = warp & 3, wn = warp >> 2;
    const int qr = lane >> 2, qc = lane & 3;
    const int m0 = blockIdx.y * 128, n0 = blockIdx.x * 128;

    const int rowb = tid >> 3;
    const int cseg = (tid & 7) * 8;
    const __half* Ag = A + (size_t)(m0 + rowb) * K + cseg;
    const __half* Wg = W + (size_t)(n0 + rowb) * K + cseg;

    float acc[2][8][4] = {};
    const int niter = K >> 6;

#pragma unroll
    for (int st = 0; st < 2; st++) {
        __half* Ad = sm + st * STGH + rowb * HP + cseg;
        __half* Bd = sm + st * STGH + 128 * HP + rowb * HP + cseg;
        int k0 = st << 6;
#pragma unroll
        for (int i = 0; i < 4; i++) cp16(Ad + i * 32 * HP, Ag + k0 + (size_t)i * 32 * K);
#pragma unroll
        for (int i = 0; i < 4; i++) cp16(Bd + i * 32 * HP, Wg + k0 + (size_t)i * 32 * K);
        cp_commit();
    }

    for (int it = 0; it < niter; it++) {
        cp_wait<1>();
        __syncthreads();
        int cur = it % 3;
        const __half* Ab = sm + cur * STGH + wm * 32 * HP;
        const __half* Bb = sm + cur * STGH + 128 * HP + wn * 64 * HP;
#pragma unroll
        for (int ks = 0; ks < 4; ks++) {
            int kb = ks * 16;
            uint32_t af[2][4], bf[8][2];
#pragma unroll
            for (int mt = 0; mt < 2; mt++)
                ldsm4(af[mt][0], af[mt][1], af[mt][2], af[mt][3],
                      Ab + (mt * 16 + (lane & 15)) * HP + kb + (lane >> 4) * 8);
#pragma unroll
            for (int nt = 0; nt < 8; nt++)
                ldsm2(bf[nt][0], bf[nt][1],
                      Bb + (nt * 8 + (lane & 7)) * HP + kb + ((lane >> 3) & 1) * 8);
#pragma unroll
            for (int mt = 0; mt < 2; mt++)
#pragma unroll
                for (int nt = 0; nt < 8; nt++)
                    mma_f16(acc[mt][nt], af[mt][0], af[mt][1], af[mt][2], af[mt][3],
                            bf[nt][0], bf[nt][1]);
        }
        if (it + 2 < niter) {
            int st = (it + 2) % 3;
            int k0 = (it + 2) << 6;
            __half* Ad = sm + st * STGH + rowb * HP + cseg;
            __half* Bd = sm + st * STGH + 128 * HP + rowb * HP + cseg;
#pragma unroll
            for (int i = 0; i < 4; i++) cp16(Ad + i * 32 * HP, Ag + k0 + (size_t)i * 32 * K);
#pragma unroll
            for (int i = 0; i < 4; i++) cp16(Bd + i * 32 * HP, Wg + k0 + (size_t)i * 32 * K);
        }
        cp_commit();
    }

    // epilogue: paired stores, row index math hoisted out of nt loop
#pragma unroll
    for (int mt = 0; mt < 2; mt++) {
        int mA = m0 + wm * 32 + mt * 16 + qr;
        int mB = mA + 8;
        int rowA, rowB, tokA = 0, tokB = 0;
        if (MODE == 0) {
            rowA = mA / NTOK; tokA = mA % NTOK;   // rowA = win
            rowB = mB / NTOK; tokB = mB % NTOK;
        } else if (MODE == 1) {
            rowA = win_row_to_xl(mA);
            rowB = win_row_to_xl(mB);
        } else {
            rowA = mA; rowB = mB;
        }
#pragma unroll
        for (int nt = 0; nt < 8; nt++) {
            int n = n0 + wn * 64 + nt * 8 + qc * 2;
            float b0 = bias[n], b1 = bias[n + 1];
            float v0 = acc[mt][nt][0] + b0, v1 = acc[mt][nt][1] + b1;
            float v2 = acc[mt][nt][2] + b0, v3 = acc[mt][nt][3] + b1;
            if (MODE == 0) {
                int head = n / 96, t = n % 96;
                *(__half2*)&((__half*)outv)[((size_t)(rowA * NHEAD + head) * NTOK + tokA) * 96 + t]
                    = __floats2half2_rn(v0, v1);
                *(__half2*)&((__half*)outv)[((size_t)(rowB * NHEAD + head) * NTOK + tokB) * 96 + t]
                    = __floats2half2_rn(v2, v3);
            } else if (MODE == 1) {
                float2 rA = *(const float2*)&res[(size_t)rowA * CDIM + n];
                float2 rB = *(const float2*)&res[(size_t)rowB * CDIM + n];
                *(float2*)&((float*)outv)[(size_t)rowA * CDIM + n] =
                    make_float2(rA.x + v0, rA.y + v1);
                *(float2*)&((float*)outv)[(size_t)rowB * CDIM + n] =
                    make_float2(rB.x + v2, rB.y + v3);
            } else if (MODE == 2) {
                float g0 = 0.5f * v0 * (1.f + erff(v0 * 0.70710678118654752f));
                float g1 = 0.5f * v1 * (1.f + erff(v1 * 0.70710678118654752f));
                float g2 = 0.5f * v2 * (1.f + erff(v2 * 0.70710678118654752f));
                float g3 = 0.5f * v3 * (1.f + erff(v3 * 0.70710678118654752f));
                *(__half2*)&((__half*)outv)[(size_t)rowA * Ncols + n] = __floats2half2_rn(g0, g1);
                *(__half2*)&((__half*)outv)[(size_t)rowB * Ncols + n] = __floats2half2_rn(g2, g3);
            } else {
                float2 rA = *(const float2*)&res[(size_t)rowA * Ncols + n];
                float2 rB = *(const float2*)&res[(size_t)rowB * Ncols + n];
                *(float2*)&((float*)outv)[(size_t)rowA * Ncols + n] =
                    make_float2(rA.x + v0, rA.y + v1);
                *(float2*)&((float*)outv)[(size_t)rowB * Ncols + n] =
                    make_float2(rB.x + v2, rB.y + v3);
            }
        }
    }
}

// ---------------- tensor-core attention: one block per (win, head) ----------------
#define QP 40
#define VP 72
__global__ void __launch_bounds__(128)
attn_tc(const __half* __restrict__ qkv, const float* __restrict__ biasp,
        __half* __restrict__ o)
{
    int wh = blockIdx.x;
    int win = wh / NHEAD, head = wh % NHEAD;
    __shared__ __half Qs[64 * QP];
    __shared__ __half Ks[64 * QP];
    __shared__ __half Vt[32 * VP];
    int tid = threadIdx.x;

    for (int i = tid; i < 64 * QP / 2; i += 128) {
        ((uint32_t*)Qs)[i] = 0;
        ((uint32_t*)Ks)[i] = 0;
    }
    for (int i = tid; i < 32 * VP / 2; i += 128) ((uint32_t*)Vt)[i] = 0;
    __syncthreads();

    const uint4* src = (const uint4*)(qkv + (size_t)wh * NTOK * 96);
    for (int idx = tid; idx < 588; idx += 128) {
        uint4 v = src[idx];
        int row = idx / 12, seg = idx % 12;
        if (seg < 4)      *(uint4*)(Qs + row * QP + seg * 8) = v;
        else if (seg < 8) *(uint4*)(Ks + row * QP + (seg - 4) * 8) = v;
        else {
            int d0 = (seg - 8) * 8;
            __half h[8];
            *(uint4*)h = v;
#pragma unroll
            for (int t = 0; t < 8; t++) Vt[(d0 + t) * VP + row] = h[t];
        }
    }
    __syncthreads();

    int warp = tid >> 5, lane = tid & 31;
    int qr = lane >> 2, qc = lane & 3;

    float sc[8][4] = {};
#pragma unroll
    for (int ks = 0; ks < 2; ks++) {
        int kb = ks * 16;
        uint32_t a0, a1, a2, a3;
        ldsm4(a0, a1, a2, a3, Qs + (warp * 16 + (lane & 15)) * QP + kb + (lane >> 4) * 8);
#pragma unroll
        for (int nt = 0; nt < 8; nt++) {
            uint32_t b0, b1;
            ldsm2(b0, b1, Ks + (nt * 8 + (lane & 7)) * QP + kb + ((lane >> 3) & 1) * 8);
            mma_f16(sc[nt], a0, a1, a2, a3, b0, b1);
        }
    }

    const float scale = 0.1767766952966369f;
    const float* bp = biasp + (head * 64 + warp * 16) * 64;
    float m0 = -1e30f, m1 = -1e30f;
#pragma unroll
    for (int nt = 0; nt < 8; nt++) {
        int col = nt * 8 + qc * 2;
        sc[nt][0] = fmaf(sc[nt][0], scale, bp[qr * 64 + col]);
        sc[nt][1] = fmaf(sc[nt][1], scale, bp[qr * 64 + col + 1]);
        sc[nt][2] = fmaf(sc[nt][2], scale, bp[(qr + 8) * 64 + col]);
        sc[nt][3] = fmaf(sc[nt][3], scale, bp[(qr + 8) * 64 + col + 1]);
        m0 = fmaxf(m0, fmaxf(sc[nt][0], sc[nt][1]));
        m1 = fmaxf(m1, fmaxf(sc[nt][2], sc[nt][3]));
    }
#pragma unroll
    for (int off = 1; off < 4; off <<= 1) {
        m0 = fmaxf(m0, __shfl_xor_sync(0xffffffffu, m0, off));
        m1 = fmaxf(m1, __shfl_xor_sync(0xffffffffu, m1, off));
    }
    float s0 = 0.f, s1 = 0.f;
#pragma unroll
    for (int nt = 0; nt < 8; nt++) {
        sc[nt][0] = __expf(sc[nt][0] - m0);
        sc[nt][1] = __expf(sc[nt][1] - m0);
        sc[nt][2] = __expf(sc[nt][2] - m1);
        sc[nt][3] = __expf(sc[nt][3] - m1);
        s0 += sc[nt][0] + sc[nt][1];
        s1 += sc[nt][2] + sc[nt][3];
    }
#pragma unroll
    for (int off = 1; off < 4; off <<= 1) {
        s0 += __shfl_xor_sync(0xffffffffu, s0, off);
        s1 += __shfl_xor_sync(0xffffffffu, s1, off);
    }
    float i0 = 1.f / s0, i1 = 1.f / s1;
    uint32_t p01[8], p23[8];
#pragma unroll
    for (int nt = 0; nt < 8; nt++) {
        p01[nt] = h2u(__floats2half2_rn(sc[nt][0] * i0, sc[nt][1] * i0));
        p23[nt] = h2u(__floats2half2_rn(sc[nt][2] * i1, sc[nt][3] * i1));
    }

    float oc[4][4] = {};
#pragma unroll
    for (int ks = 0; ks < 4; ks++) {
        uint32_t a0 = p01[2 * ks], a1 = p23[2 * ks];
        uint32_t a2 = p01[2 * ks + 1], a3 = p23[2 * ks + 1];
#pragma unroll
        for (int nt = 0; nt < 4; nt++) {
            uint32_t b0, b1;
            ldsm2(b0, b1, Vt + (nt * 8 + (lane & 7)) * VP + ks * 16 + ((lane >> 3) & 1) * 8);
            mma_f16(oc[nt], a0, a1, a2, a3, b0, b1);
        }
    }

    int r0 = warp * 16 + qr, r1 = r0 + 8;
#pragma unroll
    for (int nt = 0; nt < 4; nt++) {
        int col = head * KDIM + nt * 8 + qc * 2;
        if (r0 < NTOK)
            *(__half2*)&o[((size_t)(win * NTOK + r0)) * CDIM + col] =
                __floats2half2_rn(oc[nt][0], oc[nt][1]);
        if (r1 < NTOK)
            *(__half2*)&o[((size_t)(win * NTOK + r1)) * CDIM + col] =
                __floats2half2_rn(oc[nt][2], oc[nt][3]);
    }
}

// ---------------- depthwise conv + BN + LN: one block per (b,h) row, sliding window ----------------
__global__ void __launch_bounds__(384)
conv_bn_ln(const float* __restrict__ x1, const float* __restrict__ cw,
           const float* __restrict__ bng, const float* __restrict__ bnb,
           const float* __restrict__ bnm, const float* __restrict__ bnv,
           const float* __restrict__ lng, const float* __restrict__ lnb,
           float* __restrict__ x2, __half* __restrict__ xn)
{
    __shared__ float sv[HDIM][CDIM];
    int bh = blockIdx.x;
    int b = bh / HDIM, h = bh % HDIM;
    int c = threadIdx.x;

    // per-channel weights and BN constants
    float k[3][3];
#pragma unroll
    for (int r = 0; r < 3; r++)
#pragma unroll
        for (int q = 0; q < 3; q++) k[r][q] = cw[c * 9 + r * 3 + q];
    float bninv = rsqrtf(bnv[c] + 1e-5f);
    float bscale = bng[c] * bninv;
    float bm = bnm[c], bb = bnb[c];

    const float* rows[3];
    bool rv[3];
#pragma unroll
    for (int r = 0; r < 3; r++) {
        int hh = h + r - 1;
        rv[r] = (hh >= 0 && hh < HDIM);
        rows[r] = x1 + ((size_t)b * LDIM + (rv[r] ? hh : 0) * HDIM) * CDIM + c;
    }

    float colA[3] = {0.f, 0.f, 0.f};   // w-1
    float colB[3], colC[3];            // w, w+1
#pragma unroll
    for (int r = 0; r < 3; r++) colB[r] = rv[r] ? rows[r][0] : 0.f;
#pragma unroll
    for (int r = 0; r < 3; r++) colC[r] = rv[r] ? rows[r][(size_t)CDIM] : 0.f;

    for (int w = 0; w < HDIM; w++) {
        float acc = 0.f;
#pragma unroll
        for (int r = 0; r < 3; r++) {
            acc = fmaf(colA[r], k[r][0], acc);
            acc = fmaf(colB[r], k[r][1], acc);
            acc = fmaf(colC[r], k[r][2], acc);
        }
        // BN: (acc - mean) * (gamma*inv) + beta, matching original op order
        float v = (acc - bm) * bscale + bb;
        sv[w][c] = v;
        // slide
#pragma unroll
        for (int r = 0; r < 3; r++) { colA[r] = colB[r]; colB[r] = colC[r]; }
        int wn2 = w + 2;
        if (wn2 < HDIM) {
#pragma unroll
            for (int r = 0; r < 3; r++)
                colC[r] = rv[r] ? rows[r][(size_t)wn2 * CDIM] : 0.f;
        } else {
#pragma unroll
            for (int r = 0; r < 3; r++) colC[r] = 0.f;
        }
    }
    __syncthreads();

    // LN per pixel: 12 warps, warp handles pixels warp, warp+12, warp+24
    int warp = threadIdx.x >> 5, lane = threadIdx.x & 31;
    for (int p = warp; p < HDIM; p += 12) {
        float vals[12];
        float s = 0.f, s2 = 0.f;
#pragma unroll
        for (int i = 0; i < 12; i++) {
            float v = sv[p][lane + 32 * i];
            vals[i] = v;
            s += v;
            s2 = fmaf(v, v, s2);
        }
#pragma unroll
        for (int o = 16; o; o >>= 1) {
            s  += __shfl_xor_sync(0xffffffffu, s,  o);
            s2 += __shfl_xor_sync(0xffffffffu, s2, o);
        }
        float mean = s * (1.f / CDIM);
        float var  = s2 * (1.f / CDIM) - mean * mean;
        float inv  = rsqrtf(var + 1e-5f);
        size_t base = ((size_t)b * LDIM + h * HDIM + p) * CDIM;
#pragma unroll
        for (int i = 0; i < 12; i++) {
            int ch = lane + 32 * i;
            x2[base + ch] = vals[i];
            xn[base + ch] = __float2half_rn((vals[i] - mean) * inv * lng[ch] + lnb[ch]);
        }
    }
}

// ---------------- launch ----------------
static void* symptr(const void* s) {
    void* p = nullptr;
    cudaGetSymbolAddress(&p, s);
    return p;
}

extern "C" void kernel_launch(void* const* d_in, const int* in_sizes, int n_in,
                              void* d_out, int out_size)
{
    const float* x        = (const float*)d_in[0];
    const float* ln_a_g   = (const float*)d_in[1];
    const float* ln_a_b   = (const float*)d_in[2];
    const float* qkv_w    = (const float*)d_in[3];
    const float* qkv_b    = (const float*)d_in[4];
    const float* attn_bias= (const float*)d_in[5];
    const float* proj_w   = (const float*)d_in[6];
    const float* proj_b   = (const float*)d_in[7];
    const float* conv_w   = (const float*)d_in[8];
    const float* bn_g     = (const float*)d_in[9];
    const float* bn_b     = (const float*)d_in[10];
    const float* bn_m     = (const float*)d_in[11];
    const float* bn_v     = (const float*)d_in[12];
    const float* ln_m_g   = (const float*)d_in[13];
    const float* ln_m_b   = (const float*)d_in[14];
    const float* fc1_w    = (const float*)d_in[15];
    const float* fc1_b    = (const float*)d_in[16];
    const float* fc2_w    = (const float*)d_in[17];
    const float* fc2_b    = (const float*)d_in[18];
    const int*   bias_idxs= (const int*)d_in[19];
    float* out = (float*)d_out;

    __half* xn    = (__half*)symptr(g_xn);
    __half* qkv   = (__half*)symptr(g_qkv);
    __half* ob    = (__half*)symptr(g_o);
    float*  x1    = (float*)symptr(g_x1);
    float*  x2    = (float*)symptr(g_x2);
    __half* hmid  = (__half*)symptr(g_hmid);
    __half* wbuf  = (__half*)symptr(g_wh);
    float*  biasp = (float*)symptr(g_biasp);

    __half* wq = wbuf;
    __half* wp = wbuf + WN0;
    __half* w1 = wbuf + WN1;
    __half* w2 = wbuf + WN2;

    cudaFuncSetAttribute(gemm_h<0>, cudaFuncAttributeMaxDynamicSharedMemorySize, GEMM_SMEM);
    cudaFuncSetAttribute(gemm_h<1>, cudaFuncAttributeMaxDynamicSharedMemorySize, GEMM_SMEM);
    cudaFuncSetAttribute(gemm_h<2>, cudaFuncAttributeMaxDynamicSharedMemorySize, GEMM_SMEM);
    cudaFuncSetAttribute(gemm_h<3>, cudaFuncAttributeMaxDynamicSharedMemorySize, GEMM_SMEM);

    w2h_all<<<WN3 / 1024, 256>>>(qkv_w, proj_w, fc1_w, fc2_w, wbuf);
    bias_prep<<<NHEAD, 256>>>(attn_bias, bias_idxs, biasp);

    ln_kernel<<<MROWS / 8, 256>>>(x, ln_a_g, ln_a_b, xn);
    gemm_h<0><<<dim3(QKVO / 128, MROWS / 128), 256, GEMM_SMEM>>>(xn, wq, qkv_b, qkv, CDIM, QKVO, nullptr);
    attn_tc<<<NWIN * NHEAD, 128>>>(qkv, biasp, ob);
    gemm_h<1><<<dim3(CDIM / 128, MROWS / 128), 256, GEMM_SMEM>>>(ob, wp, proj_b, x1, CDIM, CDIM, x);
    conv_bn_ln<<<BDIM * HDIM, 384>>>(x1, conv_w, bn_g, bn_b, bn_m, bn_v,
                                     ln_m_g, ln_m_b, x2, xn);
    gemm_h<2><<<dim3(HIDD / 128, MROWS / 128), 256, GEMM_SMEM>>>(xn, w1, fc1_b, hmid, CDIM, HIDD, nullptr);
    gemm_h<3><<<dim3(CDIM / 128, MROWS / 128), 256, GEMM_SMEM>>>(hmid, w2, fc2_b, out, HIDD, CDIM, x2);
}